// round 1
// baseline (speedup 1.0000x reference)
#include <cuda_runtime.h>

#define T_STEPS 2048
#define BATCH   256
#define D_IN    16
#define H1      5
#define H2      50
#define NC      20
#define G1      20    // 4*H1
#define G2      200   // 4*H2

__device__ __forceinline__ float sigmoidf_(float v) {
    return 1.0f / (1.0f + __expf(-v));
}

// One block per batch element. 256 threads:
//   tid 0..199   : layer-2 gate threads (one gate each, weights in registers)
//   tid 200..219 : layer-1 gate threads (one gate each)
//   tid 240..255 : x prefetch threads
// Update phase: tid 0..49 update (c2,h2); tid 200..204 update (c1,h1).
// Pipeline: layer-1 computes h1[k] while layer-2 consumes h1[k-1].
__global__ __launch_bounds__(256, 2)
void lstm_fused_kernel(const float* __restrict__ x,
                       const float* __restrict__ W1ih, const float* __restrict__ W1hh,
                       const float* __restrict__ b1ih, const float* __restrict__ b1hh,
                       const float* __restrict__ W2ih, const float* __restrict__ W2hh,
                       const float* __restrict__ b2ih, const float* __restrict__ b2hh,
                       const float* __restrict__ Wfc,  const float* __restrict__ bfc,
                       float* __restrict__ out)
{
    const int b   = blockIdx.x;
    const int tid = threadIdx.x;

    __shared__ __align__(16) float h2s[52];        // h2 state, padded to 13 float4
    __shared__ __align__(16) float h1buf[2][8];    // h1 double buffer, padded
    __shared__ __align__(16) float xs[2][16];      // x double buffer
    __shared__ float acts2[200];
    __shared__ float acts1[20];

    // Unified per-thread weight storage so L1/L2 threads share registers:
    //  L2 gate thread g (<200): wA[0..51] = W2hh row g (padded), wB[0..7] = W2ih row g (padded)
    //  L1 gate thread 200+g    : wA[0..15] = W1ih row g, wA[16..23] = W1hh row g (padded)
    float wA[52];
    float wB[8];
    float bias = 0.0f;
    float c2 = 0.0f, c1 = 0.0f;

    if (tid < G2) {
        #pragma unroll
        for (int k = 0; k < 52; k++) wA[k] = (k < H2) ? W2hh[tid * H2 + k] : 0.0f;
        #pragma unroll
        for (int k = 0; k < 8; k++)  wB[k] = (k < H1) ? W2ih[tid * H1 + k] : 0.0f;
        bias = b2ih[tid] + b2hh[tid];
    } else if (tid < 200 + G1) {
        const int g = tid - 200;
        #pragma unroll
        for (int k = 0; k < 16; k++) wA[k] = W1ih[g * D_IN + k];
        #pragma unroll
        for (int k = 0; k < 8; k++)  wA[16 + k] = (k < H1) ? W1hh[g * H1 + k] : 0.0f;
        bias = b1ih[g] + b1hh[g];
    }

    // Zero-init states / padding
    if (tid < 52) h2s[tid] = 0.0f;
    if (tid < 8)  { h1buf[0][tid] = 0.0f; h1buf[1][tid] = 0.0f; }
    const float* xb = x + (size_t)b * T_STEPS * D_IN;
    if (tid < 16) xs[0][tid] = xb[tid];   // x[0]
    __syncthreads();

    for (int k = 0; k <= T_STEPS; k++) {
        const int cur  = k & 1;
        const int prev = (k - 1) & 1;

        // ---- gate phase ----
        if (tid < G2) {
            if (k > 0) {
                const float4* h1v = (const float4*)h1buf[prev];
                const float4* h2v = (const float4*)h2s;
                float acc = bias;
                #pragma unroll
                for (int q = 0; q < 2; q++) {
                    float4 v = h1v[q];
                    acc += v.x * wB[4*q] + v.y * wB[4*q+1] + v.z * wB[4*q+2] + v.w * wB[4*q+3];
                }
                #pragma unroll
                for (int q = 0; q < 13; q++) {
                    float4 v = h2v[q];
                    acc += v.x * wA[4*q] + v.y * wA[4*q+1] + v.z * wA[4*q+2] + v.w * wA[4*q+3];
                }
                const int gt = tid / H2;   // 0=i,1=f,2=g,3=o
                acts2[tid] = (gt == 2) ? tanhf(acc) : sigmoidf_(acc);
            }
        } else if (tid < 200 + G1) {
            if (k < T_STEPS) {
                const float4* xv  = (const float4*)xs[cur];
                const float4* h1v = (const float4*)h1buf[prev];
                float acc = bias;
                #pragma unroll
                for (int q = 0; q < 4; q++) {
                    float4 v = xv[q];
                    acc += v.x * wA[4*q] + v.y * wA[4*q+1] + v.z * wA[4*q+2] + v.w * wA[4*q+3];
                }
                #pragma unroll
                for (int q = 0; q < 2; q++) {
                    float4 v = h1v[q];
                    acc += v.x * wA[16+4*q] + v.y * wA[16+4*q+1] + v.z * wA[16+4*q+2] + v.w * wA[16+4*q+3];
                }
                const int g  = tid - 200;
                const int gt = g / H1;
                acts1[g] = (gt == 2) ? tanhf(acc) : sigmoidf_(acc);
            }
        } else if (tid >= 240) {
            // prefetch x[k+1] into the buffer not read this iteration
            if (k + 1 < T_STEPS) {
                const int j = tid - 240;
                xs[(k + 1) & 1][j] = xb[(size_t)(k + 1) * D_IN + j];
            }
        }
        __syncthreads();

        // ---- update phase ----
        if (tid < H2) {
            if (k > 0) {
                const float gi = acts2[tid];
                const float gf = acts2[50 + tid];
                const float gg = acts2[100 + tid];
                const float go = acts2[150 + tid];
                c2 = gf * c2 + gi * gg;
                h2s[tid] = go * tanhf(c2);
            }
        } else if (tid >= 200 && tid < 200 + H1) {
            if (k < T_STEPS) {
                const int j = tid - 200;
                const float gi = acts1[j];
                const float gf = acts1[5 + j];
                const float gg = acts1[10 + j];
                const float go = acts1[15 + j];
                c1 = gf * c1 + gi * gg;
                h1buf[cur][j] = go * tanhf(c1);
            }
        }
        __syncthreads();
    }

    // ---- epilogue: result = h2_last @ Wfc.T + bfc ; also emit h2_last ----
    if (tid < NC) {
        float acc = bfc[tid];
        #pragma unroll
        for (int k = 0; k < H2; k++) acc += h2s[k] * Wfc[tid * H2 + k];
        out[b * NC + tid] = acc;
    }
    if (tid >= 32 && tid < 32 + H2) {
        const int j = tid - 32;
        out[BATCH * NC + b * H2 + j] = h2s[j];
    }
}

extern "C" void kernel_launch(void* const* d_in, const int* in_sizes, int n_in,
                              void* d_out, int out_size)
{
    (void)in_sizes; (void)n_in; (void)out_size;
    const float* x    = (const float*)d_in[0];
    const float* W1ih = (const float*)d_in[1];
    const float* W1hh = (const float*)d_in[2];
    const float* b1ih = (const float*)d_in[3];
    const float* b1hh = (const float*)d_in[4];
    const float* W2ih = (const float*)d_in[5];
    const float* W2hh = (const float*)d_in[6];
    const float* b2ih = (const float*)d_in[7];
    const float* b2hh = (const float*)d_in[8];
    const float* Wfc  = (const float*)d_in[9];
    const float* bfc  = (const float*)d_in[10];

    lstm_fused_kernel<<<BATCH, 256>>>(x, W1ih, W1hh, b1ih, b1hh,
                                      W2ih, W2hh, b2ih, b2hh,
                                      Wfc, bfc, (float*)d_out);
}